// round 1
// baseline (speedup 1.0000x reference)
#include <cuda_runtime.h>

#define D_MODEL 1024
#define N_HEADS 16
#define D_HEAD  64
#define BATCH   2
#define SEQ     2048
#define M_ROWS  (BATCH * SEQ)      // 4096
#define BQ      64
#define LDT     65                 // padded leading dim for transposed smem tiles

// ---------------- scratch (no allocations allowed) ----------------
__device__ float g_Q[(size_t)BATCH * N_HEADS * SEQ * D_HEAD];   // [B*H, S, Dh]
__device__ float g_K[(size_t)BATCH * N_HEADS * SEQ * D_HEAD];
__device__ float g_V[(size_t)BATCH * N_HEADS * SEQ * D_HEAD];
__device__ float g_A[(size_t)M_ROWS * D_MODEL];                 // attn out [B,S,D]

// ---------------- GEMM: out = A[M,K] @ W[K,N] (+bias) ----------------
// mode 0/1/2: A = X, scatter result into g_Q/g_K/g_V as [B,H,S,Dh] (with bias)
// mode 3   : A = g_A, write row-major to out (no bias)
__global__ __launch_bounds__(256) void gemm_kernel(
        const float* __restrict__ X, const float* __restrict__ W,
        const float* __restrict__ bias, float* __restrict__ out, int mode)
{
    const int K = D_MODEL, N = D_MODEL;
    __shared__ float As[16][64];   // As[k][m]  (A tile transposed)
    __shared__ float Bs[16][64];   // Bs[k][n]

    const float* A = (mode == 3) ? g_A : X;

    const int tid = threadIdx.x;
    const int ty = tid >> 4, tx = tid & 15;
    const int rowBase = blockIdx.y * 64;
    const int colBase = blockIdx.x * 64;

    float acc[4][4];
#pragma unroll
    for (int r = 0; r < 4; r++)
#pragma unroll
        for (int c = 0; c < 4; c++) acc[r][c] = 0.f;

    const int ar = tid >> 2, aq = tid & 3;     // A tile: 64 rows x 4 float4
    const int br = tid >> 4, bq = tid & 15;    // B tile: 16 rows x 16 float4

    for (int k0 = 0; k0 < K; k0 += 16) {
        float4 av = *(const float4*)(A + (size_t)(rowBase + ar) * K + k0 + aq * 4);
        As[aq * 4 + 0][ar] = av.x;
        As[aq * 4 + 1][ar] = av.y;
        As[aq * 4 + 2][ar] = av.z;
        As[aq * 4 + 3][ar] = av.w;
        *(float4*)(&Bs[br][bq * 4]) =
            *(const float4*)(W + (size_t)(k0 + br) * N + colBase + bq * 4);
        __syncthreads();
#pragma unroll
        for (int kk = 0; kk < 16; kk++) {
            float a[4], b[4];
#pragma unroll
            for (int r = 0; r < 4; r++) a[r] = As[kk][ty * 4 + r];
#pragma unroll
            for (int c = 0; c < 4; c++) b[c] = Bs[kk][tx * 4 + c];
#pragma unroll
            for (int r = 0; r < 4; r++)
#pragma unroll
                for (int c = 0; c < 4; c++) acc[r][c] += a[r] * b[c];
        }
        __syncthreads();
    }

#pragma unroll
    for (int r = 0; r < 4; r++) {
        const int row = rowBase + ty * 4 + r;
#pragma unroll
        for (int c = 0; c < 4; c++) {
            const int col = colBase + tx * 4 + c;
            float v = acc[r][c];
            if (mode < 3) {
                v += bias[col];
                const int b = row >> 11, s = row & (SEQ - 1);
                const int h = col >> 6,  d = col & (D_HEAD - 1);
                float* dst = (mode == 0) ? g_Q : (mode == 1) ? g_K : g_V;
                dst[(((size_t)(b * N_HEADS + h)) * SEQ + s) * D_HEAD + d] = v;
            } else {
                out[(size_t)row * N + col] = v;
            }
        }
    }
}

// ---------------- Flash attention (fp32, causal) ----------------
// grid: (S/BQ=32, N_HEADS, BATCH), 256 threads
__global__ __launch_bounds__(256) void flash_kernel()
{
    extern __shared__ float sm[];
    float* sQT = sm;                       // [64][LDT]  Q^T  (d-major)
    float* sKT = sQT + 64 * LDT;           // [64][LDT]  K^T  (d-major)
    float* sV  = sKT + 64 * LDT;           // [64][64]   V    (k-major)
    float* sP  = sV  + 64 * 64;            // [64][LDT]  P^T  (k-major rows, q cols)
    float* s_m = sP  + 64 * LDT;
    float* s_l = s_m + 64;
    float* s_c = s_l + 64;

    const int tid = threadIdx.x;
    const int ty = tid >> 4, tx = tid & 15;
    const int qt = blockIdx.x;
    const int h  = blockIdx.y;
    const int b  = blockIdx.z;
    const size_t base = (size_t)(b * N_HEADS + h) * SEQ * D_HEAD;
    const int qBase = qt * BQ;

    // load Q tile transposed, pre-scaled by 1/sqrt(Dh)
    for (int i = tid; i < BQ * D_HEAD; i += 256) {
        const int r = i >> 6, d = i & 63;
        sQT[d * LDT + r] = g_Q[base + (size_t)(qBase + r) * D_HEAD + d] * 0.125f;
    }
    if (tid < 64) { s_m[tid] = -3.0e38f; s_l[tid] = 0.f; }

    float acc[4][4];
#pragma unroll
    for (int r = 0; r < 4; r++)
#pragma unroll
        for (int c = 0; c < 4; c++) acc[r][c] = 0.f;
    __syncthreads();

    const int nT = qt + 1;   // causal: only key tiles <= query tile
    for (int jt = 0; jt < nT; jt++) {
        const int kBase = jt * BQ;
        for (int i = tid; i < BQ * D_HEAD; i += 256) {
            const int r = i >> 6, d = i & 63;
            sKT[d * LDT + r] = g_K[base + (size_t)(kBase + r) * D_HEAD + d];
        }
        for (int i = tid * 4; i < BQ * D_HEAD; i += 1024) {
            *(float4*)(sV + i) = *(const float4*)(g_V + base + (size_t)kBase * D_HEAD + i);
        }
        __syncthreads();

        // S = Q K^T
        float s[4][4];
#pragma unroll
        for (int r = 0; r < 4; r++)
#pragma unroll
            for (int c = 0; c < 4; c++) s[r][c] = 0.f;
#pragma unroll 8
        for (int d = 0; d < D_HEAD; d++) {
            float a[4], bb[4];
#pragma unroll
            for (int r = 0; r < 4; r++) a[r]  = sQT[d * LDT + ty * 4 + r];
#pragma unroll
            for (int c = 0; c < 4; c++) bb[c] = sKT[d * LDT + tx * 4 + c];
#pragma unroll
            for (int r = 0; r < 4; r++)
#pragma unroll
                for (int c = 0; c < 4; c++) s[r][c] += a[r] * bb[c];
        }
        // causal mask (only needed on the diagonal tile)
        if (jt == qt) {
#pragma unroll
            for (int r = 0; r < 4; r++)
#pragma unroll
                for (int c = 0; c < 4; c++)
                    if (kBase + tx * 4 + c > qBase + ty * 4 + r) s[r][c] = -1e30f;
        }
        // stage scores (transposed: [k][q]) for row-wise softmax
#pragma unroll
        for (int r = 0; r < 4; r++)
#pragma unroll
            for (int c = 0; c < 4; c++)
                sP[(tx * 4 + c) * LDT + ty * 4 + r] = s[r][c];
        __syncthreads();

        // online softmax row stats: one thread per query row
        if (tid < 64) {
            const int row = tid;
            const float m_old = s_m[row];
            float mt = m_old;
#pragma unroll 8
            for (int k = 0; k < BQ; k++) mt = fmaxf(mt, sP[k * LDT + row]);
            float sum = 0.f;
#pragma unroll 8
            for (int k = 0; k < BQ; k++) {
                const float p = expf(sP[k * LDT + row] - mt);
                sP[k * LDT + row] = p;
                sum += p;
            }
            const float cc = expf(m_old - mt);
            s_c[row] = cc;
            s_l[row] = cc * s_l[row] + sum;
            s_m[row] = mt;
        }
        __syncthreads();

        // rescale accumulator, then O += P @ V
        float cr[4];
#pragma unroll
        for (int r = 0; r < 4; r++) cr[r] = s_c[ty * 4 + r];
#pragma unroll
        for (int r = 0; r < 4; r++)
#pragma unroll
            for (int c = 0; c < 4; c++) acc[r][c] *= cr[r];
#pragma unroll 8
        for (int k = 0; k < BQ; k++) {
            float a[4], v[4];
#pragma unroll
            for (int r = 0; r < 4; r++) a[r] = sP[k * LDT + ty * 4 + r];
#pragma unroll
            for (int c = 0; c < 4; c++) v[c] = sV[k * 64 + tx * 4 + c];
#pragma unroll
            for (int r = 0; r < 4; r++)
#pragma unroll
                for (int c = 0; c < 4; c++) acc[r][c] += a[r] * v[c];
        }
        __syncthreads();
    }

    // normalize and write to g_A as [B, S, D]
#pragma unroll
    for (int r = 0; r < 4; r++) {
        const float inv = 1.f / s_l[ty * 4 + r];
        float4 o;
        o.x = acc[r][0] * inv; o.y = acc[r][1] * inv;
        o.z = acc[r][2] * inv; o.w = acc[r][3] * inv;
        const size_t row = (size_t)(b * SEQ + qBase + ty * 4 + r);
        *(float4*)(g_A + row * D_MODEL + h * D_HEAD + tx * 4) = o;
    }
}

// ---------------- launch ----------------
extern "C" void kernel_launch(void* const* d_in, const int* in_sizes, int n_in,
                              void* d_out, int out_size)
{
    const float* x  = (const float*)d_in[0];
    const float* Wq = (const float*)d_in[1];
    const float* bq = (const float*)d_in[2];
    const float* Wk = (const float*)d_in[3];
    const float* bk = (const float*)d_in[4];
    const float* Wv = (const float*)d_in[5];
    const float* bv = (const float*)d_in[6];
    const float* Wo = (const float*)d_in[7];
    float* out = (float*)d_out;

    const dim3 gGemm(D_MODEL / 64, M_ROWS / 64);   // 16 x 64

    gemm_kernel<<<gGemm, 256>>>(x, Wq, bq, nullptr, 0);
    gemm_kernel<<<gGemm, 256>>>(x, Wk, bk, nullptr, 1);
    gemm_kernel<<<gGemm, 256>>>(x, Wv, bv, nullptr, 2);

    const int smemBytes = (64 * LDT * 3 + 64 * 64 + 192) * (int)sizeof(float); // 67072
    cudaFuncSetAttribute(flash_kernel, cudaFuncAttributeMaxDynamicSharedMemorySize, smemBytes);
    flash_kernel<<<dim3(SEQ / BQ, N_HEADS, BATCH), 256, smemBytes>>>();

    gemm_kernel<<<gGemm, 256>>>(nullptr, Wo, nullptr, out, 3);
}

// round 4
// speedup vs baseline: 1.4856x; 1.4856x over previous
#include <cuda_runtime.h>
#include <cuda_bf16.h>
#include <cstdint>

#define D_MODEL 1024
#define N_HEADS 16
#define D_HEAD  64
#define BATCH   2
#define SEQ     2048
#define M_ROWS  (BATCH * SEQ)      // 4096
#define BQ      64
#define LDT     65

// ---------------- scratch (no allocations allowed) ----------------
__device__ float g_Q[(size_t)BATCH * N_HEADS * SEQ * D_HEAD];
__device__ float g_K[(size_t)BATCH * N_HEADS * SEQ * D_HEAD];
__device__ float g_V[(size_t)BATCH * N_HEADS * SEQ * D_HEAD];
__device__ float g_A[(size_t)M_ROWS * D_MODEL];

// bf16 split-precision operands
__device__ __nv_bfloat16 g_xh[(size_t)M_ROWS * D_MODEL];
__device__ __nv_bfloat16 g_xl[(size_t)M_ROWS * D_MODEL];
__device__ __nv_bfloat16 g_Ah[(size_t)M_ROWS * D_MODEL];
__device__ __nv_bfloat16 g_Al[(size_t)M_ROWS * D_MODEL];
__device__ __nv_bfloat16 g_Wth[(size_t)4 * D_MODEL * D_MODEL];  // W^T hi, [4][n][k]
__device__ __nv_bfloat16 g_Wtl[(size_t)4 * D_MODEL * D_MODEL];  // W^T lo

// ---------------- helpers ----------------
__device__ __forceinline__ uint32_t smem_u32(const void* p) {
    uint32_t a;
    asm("{ .reg .u64 t; cvta.to.shared.u64 t, %1; cvt.u32.u64 %0, t; }" : "=r"(a) : "l"(p));
    return a;
}
__device__ __forceinline__ void cp_async16(uint32_t sa, const void* g) {
    asm volatile("cp.async.cg.shared.global [%0], [%1], 16;\n" :: "r"(sa), "l"(g));
}
__device__ __forceinline__ void ldmat4(uint32_t* r, uint32_t addr) {
    asm volatile("ldmatrix.sync.aligned.m8n8.x4.shared.b16 {%0,%1,%2,%3}, [%4];"
        : "=r"(r[0]), "=r"(r[1]), "=r"(r[2]), "=r"(r[3]) : "r"(addr));
}
__device__ __forceinline__ void mma16816(float* c, const uint32_t* a, const uint32_t* b) {
    asm volatile("mma.sync.aligned.m16n8k16.row.col.f32.bf16.bf16.f32 "
        "{%0,%1,%2,%3}, {%4,%5,%6,%7}, {%8,%9}, {%0,%1,%2,%3};"
        : "+f"(c[0]), "+f"(c[1]), "+f"(c[2]), "+f"(c[3])
        : "r"(a[0]), "r"(a[1]), "r"(a[2]), "r"(a[3]), "r"(b[0]), "r"(b[1]));
}

// ---------------- conversion kernels ----------------
__global__ __launch_bounds__(256) void cvt_rm(const float* __restrict__ xsrc, int sel)
{
    const float* src = sel ? g_A : xsrc;
    __nv_bfloat16* hi = sel ? g_Ah : g_xh;
    __nv_bfloat16* lo = sel ? g_Al : g_xl;
    const size_t i4 = (size_t)blockIdx.x * blockDim.x + threadIdx.x;
    if (i4 < (size_t)M_ROWS * D_MODEL / 4) {
        float4 v = ((const float4*)src)[i4];
        float vv[4] = {v.x, v.y, v.z, v.w};
#pragma unroll
        for (int j = 0; j < 4; j++) {
            __nv_bfloat16 h = __float2bfloat16_rn(vv[j]);
            hi[i4 * 4 + j] = h;
            lo[i4 * 4 + j] = __float2bfloat16_rn(vv[j] - __bfloat162float(h));
        }
    }
}

// transpose-convert: W[k][n] -> Wt[n][k] (hi/lo), z selects weight
__global__ __launch_bounds__(256) void cvt_wt(const float* __restrict__ Wq,
                                              const float* __restrict__ Wk,
                                              const float* __restrict__ Wv,
                                              const float* __restrict__ Wo)
{
    __shared__ float t[32][33];
    const int z = blockIdx.z;
    const float* W = (z == 0) ? Wq : (z == 1) ? Wk : (z == 2) ? Wv : Wo;
    __nv_bfloat16* hi = g_Wth + (size_t)z * D_MODEL * D_MODEL;
    __nv_bfloat16* lo = g_Wtl + (size_t)z * D_MODEL * D_MODEL;
    const int n0 = blockIdx.x * 32, k0 = blockIdx.y * 32;
    const int tx = threadIdx.x & 31, ty = threadIdx.x >> 5;   // 32 x 8
    for (int r = ty; r < 32; r += 8)
        t[r][tx] = W[(size_t)(k0 + r) * D_MODEL + n0 + tx];
    __syncthreads();
    for (int r = ty; r < 32; r += 8) {
        float v = t[tx][r];                       // = W[k0+tx][n0+r]
        __nv_bfloat16 h = __float2bfloat16_rn(v);
        const size_t o = (size_t)(n0 + r) * D_MODEL + k0 + tx;
        hi[o] = h;
        lo[o] = __float2bfloat16_rn(v - __bfloat162float(h));
    }
}

// ---------------- mma.sync split-bf16 GEMM ----------------
// CTA: 256 thr / 8 warps, tile 128x128, warp tile 32(m) x 64(n), K-chunk 32.
// mode 0: QKV (z = blockIdx.z), A = x splits; scatter +bias into g_Q/K/V
// mode 1: A = attn-out splits, W = Wo; row-major into out
#define AST   40                       // padded smem row stride (bf16)
#define TILEB (128 * AST * 2)          // 10240 bytes per tile
#define BUFB  (4 * TILEB)              // Ah, Al, Bh, Bl
#define KC    32
#define NKC   (D_MODEL / KC)           // 32 chunks

__device__ __forceinline__ void load_chunk_mma(uint32_t bufbase, int c, int tid,
        const __nv_bfloat16* g0, const __nv_bfloat16* g1,
        const __nv_bfloat16* g2, const __nv_bfloat16* g3)
{
    const __nv_bfloat16* gs[4] = {g0, g1, g2, g3};
#pragma unroll
    for (int i = 0; i < 8; i++) {
        const int idx = i * 256 + tid;
        const int t = idx >> 9;            // tile 0..3
        const int rem = idx & 511;
        const int row = rem >> 2;          // 0..127
        const int seg = rem & 3;           // 4 x 16B = 32 bf16
        const __nv_bfloat16* g = gs[t] + (size_t)row * D_MODEL + c * KC + seg * 8;
        cp_async16(bufbase + t * TILEB + row * (AST * 2) + seg * 16, g);
    }
    asm volatile("cp.async.commit_group;\n" ::: "memory");
}

__global__ __launch_bounds__(256, 1) void gemm_mma(
        const float* __restrict__ bq, const float* __restrict__ bk,
        const float* __restrict__ bv, float* __restrict__ out, int mode)
{
    extern __shared__ char smem[];
    const uint32_t sb = smem_u32(smem);
    const int tid = threadIdx.x;
    const int wid = tid >> 5, lane = tid & 31;
    const int wy = wid & 3, wx = wid >> 2;           // warp grid 4(m) x 2(n)
    const int rowBase = blockIdx.y * 128;
    const int colBase = blockIdx.x * 128;
    const int z = (mode == 0) ? blockIdx.z : 3;

    const __nv_bfloat16* Ah = ((mode == 0) ? g_xh : g_Ah) + (size_t)rowBase * D_MODEL;
    const __nv_bfloat16* Al = ((mode == 0) ? g_xl : g_Al) + (size_t)rowBase * D_MODEL;
    const __nv_bfloat16* Bh = g_Wth + (size_t)z * D_MODEL * D_MODEL + (size_t)colBase * D_MODEL;
    const __nv_bfloat16* Bl = g_Wtl + (size_t)z * D_MODEL * D_MODEL + (size_t)colBase * D_MODEL;

    const uint32_t buf0 = sb, buf1 = sb + BUFB;

    float acc[2][8][4];
#pragma unroll
    for (int mt = 0; mt < 2; mt++)
#pragma unroll
        for (int nt = 0; nt < 8; nt++)
#pragma unroll
            for (int j = 0; j < 4; j++) acc[mt][nt][j] = 0.f;

    load_chunk_mma(buf0, 0, tid, Ah, Al, Bh, Bl);
    load_chunk_mma(buf1, 1, tid, Ah, Al, Bh, Bl);

    // per-lane ldmatrix source coordinates
    const int arow = (lane & 7) + ((lane >> 3) & 1) * 8;   // + wy*32 + mt*16
    const int acol = (lane >> 4) * 8;                      // + ks*16
    const int brow = (lane & 7) + (lane >> 4) * 8;         // + wx*64 + np*16
    const int bcol = ((lane >> 3) & 1) * 8;                // + ks*16

    for (int c = 0; c < NKC; c++) {
        const int b = c & 1;
        if (c < NKC - 1) asm volatile("cp.async.wait_group 1;\n" ::: "memory");
        else             asm volatile("cp.async.wait_group 0;\n" ::: "memory");
        __syncthreads();

        const uint32_t base = b ? buf1 : buf0;
        const uint32_t aHs = base,             aLs = base + TILEB;
        const uint32_t bHs = base + 2 * TILEB, bLs = base + 3 * TILEB;

#pragma unroll
        for (int ks = 0; ks < 2; ks++) {
            uint32_t ah[2][4], al[2][4], bh[4][4], bl[4][4];
#pragma unroll
            for (int mt = 0; mt < 2; mt++) {
                const uint32_t off = (uint32_t)(wy * 32 + mt * 16 + arow) * (AST * 2)
                                   + (uint32_t)(ks * 16 + acol) * 2;
                ldmat4(ah[mt], aHs + off);
                ldmat4(al[mt], aLs + off);
            }
#pragma unroll
            for (int np = 0; np < 4; np++) {
                const uint32_t off = (uint32_t)(wx * 64 + np * 16 + brow) * (AST * 2)
                                   + (uint32_t)(ks * 16 + bcol) * 2;
                ldmat4(bh[np], bHs + off);
                ldmat4(bl[np], bLs + off);
            }
#pragma unroll
            for (int mt = 0; mt < 2; mt++)
#pragma unroll
                for (int np = 0; np < 4; np++) {
                    mma16816(acc[mt][np * 2],     ah[mt], &bh[np][0]);
                    mma16816(acc[mt][np * 2 + 1], ah[mt], &bh[np][2]);
                    mma16816(acc[mt][np * 2],     ah[mt], &bl[np][0]);
                    mma16816(acc[mt][np * 2 + 1], ah[mt], &bl[np][2]);
                    mma16816(acc[mt][np * 2],     al[mt], &bh[np][0]);
                    mma16816(acc[mt][np * 2 + 1], al[mt], &bh[np][2]);
                }
        }
        __syncthreads();
        if (c + 2 < NKC)
            load_chunk_mma(b ? buf1 : buf0, c + 2, tid, Ah, Al, Bh, Bl);
    }

    // ---------------- epilogue ----------------
    const float* bias = (z == 0) ? bq : (z == 1) ? bk : bv;
    float* dst = (z == 0) ? g_Q : (z == 1) ? g_K : g_V;
#pragma unroll
    for (int mt = 0; mt < 2; mt++) {
#pragma unroll
        for (int nt = 0; nt < 8; nt++) {
#pragma unroll
            for (int j = 0; j < 4; j++) {
                const int row = rowBase + wy * 32 + mt * 16 + (lane >> 2) + (j >> 1) * 8;
                const int col = colBase + wx * 64 + nt * 8 + (lane & 3) * 2 + (j & 1);
                const float v = acc[mt][nt][j];
                if (mode == 0) {
                    const int bb = row >> 11, s = row & (SEQ - 1);
                    const int h = col >> 6, d = col & (D_HEAD - 1);
                    dst[(((size_t)(bb * N_HEADS + h)) * SEQ + s) * D_HEAD + d] = v + bias[col];
                } else {
                    out[(size_t)row * D_MODEL + col] = v;
                }
            }
        }
    }
}

// ---------------- Flash attention (fp32, causal) — unchanged ----------------
__global__ __launch_bounds__(256) void flash_kernel()
{
    extern __shared__ float sm[];
    float* sQT = sm;
    float* sKT = sQT + 64 * LDT;
    float* sV  = sKT + 64 * LDT;
    float* sP  = sV  + 64 * 64;
    float* s_m = sP  + 64 * LDT;
    float* s_l = s_m + 64;
    float* s_c = s_l + 64;

    const int tid = threadIdx.x;
    const int ty = tid >> 4, tx = tid & 15;
    const int qt = blockIdx.x;
    const int h  = blockIdx.y;
    const int b  = blockIdx.z;
    const size_t base = (size_t)(b * N_HEADS + h) * SEQ * D_HEAD;
    const int qBase = qt * BQ;

    for (int i = tid; i < BQ * D_HEAD; i += 256) {
        const int r = i >> 6, d = i & 63;
        sQT[d * LDT + r] = g_Q[base + (size_t)(qBase + r) * D_HEAD + d] * 0.125f;
    }
    if (tid < 64) { s_m[tid] = -3.0e38f; s_l[tid] = 0.f; }

    float acc[4][4];
#pragma unroll
    for (int r = 0; r < 4; r++)
#pragma unroll
        for (int c = 0; c < 4; c++) acc[r][c] = 0.f;
    __syncthreads();

    const int nT = qt + 1;
    for (int jt = 0; jt < nT; jt++) {
        const int kBase = jt * BQ;
        for (int i = tid; i < BQ * D_HEAD; i += 256) {
            const int r = i >> 6, d = i & 63;
            sKT[d * LDT + r] = g_K[base + (size_t)(kBase + r) * D_HEAD + d];
        }
        for (int i = tid * 4; i < BQ * D_HEAD; i += 1024) {
            *(float4*)(sV + i) = *(const float4*)(g_V + base + (size_t)kBase * D_HEAD + i);
        }
        __syncthreads();

        float s[4][4];
#pragma unroll
        for (int r = 0; r < 4; r++)
#pragma unroll
            for (int c = 0; c < 4; c++) s[r][c] = 0.f;
#pragma unroll 8
        for (int d = 0; d < D_HEAD; d++) {
            float a[4], bb[4];
#pragma unroll
            for (int r = 0; r < 4; r++) a[r]  = sQT[d * LDT + ty * 4 + r];
#pragma unroll
            for (int c = 0; c < 4; c++) bb[c] = sKT[d * LDT + tx * 4 + c];
#pragma unroll
            for (int r = 0; r < 4; r++)
#pragma unroll
                for (int c = 0; c < 4; c++) s[r][c] += a[r] * bb[c];
        }
        if (jt == qt) {
#pragma unroll
            for (int r = 0; r < 4; r++)
#pragma unroll
                for (int c = 0; c < 4; c++)
                    if (kBase + tx * 4 + c > qBase + ty * 4 + r) s[r][c] = -1e30f;
        }
#pragma unroll
        for (int r = 0; r < 4; r++)
#pragma unroll
            for (int c = 0; c < 4; c++)
                sP[(tx * 4 + c) * LDT + ty * 4 + r] = s[r][c];
        __syncthreads();

        if (tid < 64) {
            const int row = tid;
            const float m_old = s_m[row];
            float mt = m_old;
#pragma unroll 8
            for (int k = 0; k < BQ; k++) mt = fmaxf(mt, sP[k * LDT + row]);
            float sum = 0.f;
#pragma unroll 8
            for (int k = 0; k < BQ; k++) {
                const float p = expf(sP[k * LDT + row] - mt);
                sP[k * LDT + row] = p;
                sum += p;
            }
            const float cc = expf(m_old - mt);
            s_c[row] = cc;
            s_l[row] = cc * s_l[row] + sum;
            s_m[row] = mt;
        }
        __syncthreads();

        float cr[4];
#pragma unroll
        for (int r = 0; r < 4; r++) cr[r] = s_c[ty * 4 + r];
#pragma unroll
        for (int r = 0; r < 4; r++)
#pragma unroll
            for (int c = 0; c < 4; c++) acc[r][c] *= cr[r];
#pragma unroll 8
        for (int k = 0; k < BQ; k++) {
            float a[4], v[4];
#pragma unroll
            for (int r = 0; r < 4; r++) a[r] = sP[k * LDT + ty * 4 + r];
#pragma unroll
            for (int c = 0; c < 4; c++) v[c] = sV[k * 64 + tx * 4 + c];
#pragma unroll
            for (int r = 0; r < 4; r++)
#pragma unroll
                for (int c = 0; c < 4; c++) acc[r][c] += a[r] * v[c];
        }
        __syncthreads();
    }

#pragma unroll
    for (int r = 0; r < 4; r++) {
        const float inv = 1.f / s_l[ty * 4 + r];
        float4 o;
        o.x = acc[r][0] * inv; o.y = acc[r][1] * inv;
        o.z = acc[r][2] * inv; o.w = acc[r][3] * inv;
        const size_t row = (size_t)(b * SEQ + qBase + ty * 4 + r);
        *(float4*)(g_A + row * D_MODEL + h * D_HEAD + tx * 4) = o;
    }
}

// ---------------- launch ----------------
extern "C" void kernel_launch(void* const* d_in, const int* in_sizes, int n_in,
                              void* d_out, int out_size)
{
    const float* x  = (const float*)d_in[0];
    const float* Wq = (const float*)d_in[1];
    const float* bq = (const float*)d_in[2];
    const float* Wk = (const float*)d_in[3];
    const float* bk = (const float*)d_in[4];
    const float* Wv = (const float*)d_in[5];
    const float* bv = (const float*)d_in[6];
    const float* Wo = (const float*)d_in[7];
    float* out = (float*)d_out;

    const int gemmSmem = 2 * BUFB;   // 81920
    cudaFuncSetAttribute(gemm_mma, cudaFuncAttributeMaxDynamicSharedMemorySize, gemmSmem);
    const int flashSmem = (64 * LDT * 3 + 64 * 64 + 192) * (int)sizeof(float);
    cudaFuncSetAttribute(flash_kernel, cudaFuncAttributeMaxDynamicSharedMemorySize, flashSmem);

    // 1. split x into bf16 hi/lo
    cvt_rm<<<(M_ROWS * D_MODEL / 4 + 255) / 256, 256>>>(x, 0);
    // 2. transpose+split all four weights
    cvt_wt<<<dim3(D_MODEL / 32, D_MODEL / 32, 4), 256>>>(Wq, Wk, Wv, Wo);
    // 3. fused QKV projections (tensor cores via mma.sync)
    gemm_mma<<<dim3(D_MODEL / 128, M_ROWS / 128, 3), 256, gemmSmem>>>(bq, bk, bv, nullptr, 0);
    // 4. attention
    flash_kernel<<<dim3(SEQ / BQ, N_HEADS, BATCH), 256, flashSmem>>>();
    // 5. split attention output
    cvt_rm<<<(M_ROWS * D_MODEL / 4 + 255) / 256, 256>>>(nullptr, 1);
    // 6. output projection
    gemm_mma<<<dim3(D_MODEL / 128, M_ROWS / 128, 1), 256, gemmSmem>>>(nullptr, nullptr, nullptr, out, 1);
}

// round 6
// speedup vs baseline: 2.8100x; 1.8915x over previous
#include <cuda_runtime.h>
#include <cuda_bf16.h>
#include <cuda_fp16.h>
#include <cstdint>

#define D_MODEL 1024
#define N_HEADS 16
#define D_HEAD  64
#define BATCH   2
#define SEQ     2048
#define M_ROWS  (BATCH * SEQ)      // 4096

// Q pre-scale: 1/sqrt(Dh) * log2(e)  (softmax computed in exp2 domain)
#define QSCALE 0.1803368801111204f

// ---------------- scratch (no allocations allowed) ----------------
__device__ __half g_Qh[(size_t)BATCH * N_HEADS * SEQ * D_HEAD];
__device__ __half g_Ql[(size_t)BATCH * N_HEADS * SEQ * D_HEAD];
__device__ __half g_Kh[(size_t)BATCH * N_HEADS * SEQ * D_HEAD];
__device__ __half g_Kl[(size_t)BATCH * N_HEADS * SEQ * D_HEAD];
__device__ __half g_Vh[(size_t)BATCH * N_HEADS * SEQ * D_HEAD];
__device__ __half g_Vl[(size_t)BATCH * N_HEADS * SEQ * D_HEAD];

__device__ __nv_bfloat16 g_xh[(size_t)M_ROWS * D_MODEL];
__device__ __nv_bfloat16 g_xl[(size_t)M_ROWS * D_MODEL];
__device__ __nv_bfloat16 g_Ah[(size_t)M_ROWS * D_MODEL];
__device__ __nv_bfloat16 g_Al[(size_t)M_ROWS * D_MODEL];
__device__ __nv_bfloat16 g_Wth[(size_t)4 * D_MODEL * D_MODEL];  // W^T hi, [4][n][k]
__device__ __nv_bfloat16 g_Wtl[(size_t)4 * D_MODEL * D_MODEL];  // W^T lo

// ---------------- helpers ----------------
__device__ __forceinline__ uint32_t smem_u32(const void* p) {
    uint32_t a;
    asm("{ .reg .u64 t; cvta.to.shared.u64 t, %1; cvt.u32.u64 %0, t; }" : "=r"(a) : "l"(p));
    return a;
}
__device__ __forceinline__ void cp_async16(uint32_t sa, const void* g) {
    asm volatile("cp.async.cg.shared.global [%0], [%1], 16;\n" :: "r"(sa), "l"(g));
}
__device__ __forceinline__ void ldmat4(uint32_t* r, uint32_t addr) {
    asm volatile("ldmatrix.sync.aligned.m8n8.x4.shared.b16 {%0,%1,%2,%3}, [%4];"
        : "=r"(r[0]), "=r"(r[1]), "=r"(r[2]), "=r"(r[3]) : "r"(addr));
}
__device__ __forceinline__ void ldmat4t(uint32_t* r, uint32_t addr) {
    asm volatile("ldmatrix.sync.aligned.m8n8.x4.trans.shared.b16 {%0,%1,%2,%3}, [%4];"
        : "=r"(r[0]), "=r"(r[1]), "=r"(r[2]), "=r"(r[3]) : "r"(addr));
}
__device__ __forceinline__ void mma_bf(float* c, const uint32_t* a, const uint32_t* b) {
    asm volatile("mma.sync.aligned.m16n8k16.row.col.f32.bf16.bf16.f32 "
        "{%0,%1,%2,%3}, {%4,%5,%6,%7}, {%8,%9}, {%0,%1,%2,%3};"
        : "+f"(c[0]), "+f"(c[1]), "+f"(c[2]), "+f"(c[3])
        : "r"(a[0]), "r"(a[1]), "r"(a[2]), "r"(a[3]), "r"(b[0]), "r"(b[1]));
}
__device__ __forceinline__ void mma_fp(float* c, const uint32_t* a, const uint32_t* b) {
    asm volatile("mma.sync.aligned.m16n8k16.row.col.f32.f16.f16.f32 "
        "{%0,%1,%2,%3}, {%4,%5,%6,%7}, {%8,%9}, {%0,%1,%2,%3};"
        : "+f"(c[0]), "+f"(c[1]), "+f"(c[2]), "+f"(c[3])
        : "r"(a[0]), "r"(a[1]), "r"(a[2]), "r"(a[3]), "r"(b[0]), "r"(b[1]));
}
__device__ __forceinline__ float fexp2(float x) {
    float r; asm("ex2.approx.f32 %0, %1;" : "=f"(r) : "f"(x)); return r;
}
__device__ __forceinline__ uint32_t pack_h2(float a, float b) {
    __half2 h = __halves2half2(__float2half_rn(a), __float2half_rn(b));
    union { __half2 h2; uint32_t u; } c; c.h2 = h; return c.u;
}

// ---------------- conversion kernels ----------------
__global__ __launch_bounds__(256) void cvt_rm(const float* __restrict__ src)
{
    const size_t i4 = (size_t)blockIdx.x * blockDim.x + threadIdx.x;
    if (i4 < (size_t)M_ROWS * D_MODEL / 4) {
        float4 v = ((const float4*)src)[i4];
        float vv[4] = {v.x, v.y, v.z, v.w};
#pragma unroll
        for (int j = 0; j < 4; j++) {
            __nv_bfloat16 h = __float2bfloat16_rn(vv[j]);
            g_xh[i4 * 4 + j] = h;
            g_xl[i4 * 4 + j] = __float2bfloat16_rn(vv[j] - __bfloat162float(h));
        }
    }
}

__global__ __launch_bounds__(256) void cvt_wt(const float* __restrict__ Wq,
                                              const float* __restrict__ Wk,
                                              const float* __restrict__ Wv,
                                              const float* __restrict__ Wo)
{
    __shared__ float t[32][33];
    const int z = blockIdx.z;
    const float* W = (z == 0) ? Wq : (z == 1) ? Wk : (z == 2) ? Wv : Wo;
    __nv_bfloat16* hi = g_Wth + (size_t)z * D_MODEL * D_MODEL;
    __nv_bfloat16* lo = g_Wtl + (size_t)z * D_MODEL * D_MODEL;
    const int n0 = blockIdx.x * 32, k0 = blockIdx.y * 32;
    const int tx = threadIdx.x & 31, ty = threadIdx.x >> 5;
    for (int r = ty; r < 32; r += 8)
        t[r][tx] = W[(size_t)(k0 + r) * D_MODEL + n0 + tx];
    __syncthreads();
    for (int r = ty; r < 32; r += 8) {
        float v = t[tx][r];
        __nv_bfloat16 h = __float2bfloat16_rn(v);
        const size_t o = (size_t)(n0 + r) * D_MODEL + k0 + tx;
        hi[o] = h;
        lo[o] = __float2bfloat16_rn(v - __bfloat162float(h));
    }
}

// ---------------- mma.sync split-bf16 GEMM ----------------
#define AST   40
#define TILEB (128 * AST * 2)
#define BUFB  (4 * TILEB)
#define KC    32
#define NKC   (D_MODEL / KC)

__device__ __forceinline__ void load_chunk_mma(uint32_t bufbase, int c, int tid,
        const __nv_bfloat16* g0, const __nv_bfloat16* g1,
        const __nv_bfloat16* g2, const __nv_bfloat16* g3)
{
    const __nv_bfloat16* gs[4] = {g0, g1, g2, g3};
#pragma unroll
    for (int i = 0; i < 8; i++) {
        const int idx = i * 256 + tid;
        const int t = idx >> 9;
        const int rem = idx & 511;
        const int row = rem >> 2;
        const int seg = rem & 3;
        const __nv_bfloat16* g = gs[t] + (size_t)row * D_MODEL + c * KC + seg * 8;
        cp_async16(bufbase + t * TILEB + row * (AST * 2) + seg * 16, g);
    }
    asm volatile("cp.async.commit_group;\n" ::: "memory");
}

__global__ __launch_bounds__(256, 1) void gemm_mma(
        const float* __restrict__ bq, const float* __restrict__ bk,
        const float* __restrict__ bv, float* __restrict__ out, int mode)
{
    extern __shared__ char smem[];
    const uint32_t sb = smem_u32(smem);
    const int tid = threadIdx.x;
    const int wid = tid >> 5, lane = tid & 31;
    const int wy = wid & 3, wx = wid >> 2;
    const int rowBase = blockIdx.y * 128;
    const int colBase = blockIdx.x * 128;
    const int z = (mode == 0) ? blockIdx.z : 3;

    const __nv_bfloat16* Ah = ((mode == 0) ? g_xh : g_Ah) + (size_t)rowBase * D_MODEL;
    const __nv_bfloat16* Al = ((mode == 0) ? g_xl : g_Al) + (size_t)rowBase * D_MODEL;
    const __nv_bfloat16* Bh = g_Wth + (size_t)z * D_MODEL * D_MODEL + (size_t)colBase * D_MODEL;
    const __nv_bfloat16* Bl = g_Wtl + (size_t)z * D_MODEL * D_MODEL + (size_t)colBase * D_MODEL;

    const uint32_t buf0 = sb, buf1 = sb + BUFB;

    float acc[2][8][4];
#pragma unroll
    for (int mt = 0; mt < 2; mt++)
#pragma unroll
        for (int nt = 0; nt < 8; nt++)
#pragma unroll
            for (int j = 0; j < 4; j++) acc[mt][nt][j] = 0.f;

    load_chunk_mma(buf0, 0, tid, Ah, Al, Bh, Bl);
    load_chunk_mma(buf1, 1, tid, Ah, Al, Bh, Bl);

    const int arow = (lane & 7) + ((lane >> 3) & 1) * 8;
    const int acol = (lane >> 4) * 8;
    const int brow = (lane & 7) + (lane >> 4) * 8;
    const int bcol = ((lane >> 3) & 1) * 8;

    for (int c = 0; c < NKC; c++) {
        const int b = c & 1;
        if (c < NKC - 1) asm volatile("cp.async.wait_group 1;\n" ::: "memory");
        else             asm volatile("cp.async.wait_group 0;\n" ::: "memory");
        __syncthreads();

        const uint32_t base = b ? buf1 : buf0;
        const uint32_t aHs = base,             aLs = base + TILEB;
        const uint32_t bHs = base + 2 * TILEB, bLs = base + 3 * TILEB;

#pragma unroll
        for (int ks = 0; ks < 2; ks++) {
            uint32_t ah[2][4], al[2][4], bh[4][4], bl[4][4];
#pragma unroll
            for (int mt = 0; mt < 2; mt++) {
                const uint32_t off = (uint32_t)(wy * 32 + mt * 16 + arow) * (AST * 2)
                                   + (uint32_t)(ks * 16 + acol) * 2;
                ldmat4(ah[mt], aHs + off);
                ldmat4(al[mt], aLs + off);
            }
#pragma unroll
            for (int np = 0; np < 4; np++) {
                const uint32_t off = (uint32_t)(wx * 64 + np * 16 + brow) * (AST * 2)
                                   + (uint32_t)(ks * 16 + bcol) * 2;
                ldmat4(bh[np], bHs + off);
                ldmat4(bl[np], bLs + off);
            }
#pragma unroll
            for (int mt = 0; mt < 2; mt++)
#pragma unroll
                for (int np = 0; np < 4; np++) {
                    mma_bf(acc[mt][np * 2],     ah[mt], &bh[np][0]);
                    mma_bf(acc[mt][np * 2 + 1], ah[mt], &bh[np][2]);
                    mma_bf(acc[mt][np * 2],     ah[mt], &bl[np][0]);
                    mma_bf(acc[mt][np * 2 + 1], ah[mt], &bl[np][2]);
                    mma_bf(acc[mt][np * 2],     al[mt], &bh[np][0]);
                    mma_bf(acc[mt][np * 2 + 1], al[mt], &bh[np][2]);
                }
        }
        __syncthreads();
        if (c + 2 < NKC)
            load_chunk_mma(b ? buf1 : buf0, c + 2, tid, Ah, Al, Bh, Bl);
    }

    // ---------------- epilogue ----------------
    if (mode == 0) {
        const float* bias = (z == 0) ? bq : (z == 1) ? bk : bv;
        __half* dH = (z == 0) ? g_Qh : (z == 1) ? g_Kh : g_Vh;
        __half* dL = (z == 0) ? g_Ql : (z == 1) ? g_Kl : g_Vl;
        const float sc = (z == 0) ? QSCALE : 1.0f;
#pragma unroll
        for (int mt = 0; mt < 2; mt++) {
#pragma unroll
            for (int nt = 0; nt < 8; nt++) {
                const int col0 = colBase + wx * 64 + nt * 8 + (lane & 3) * 2;
                const int hh = col0 >> 6, d0 = col0 & (D_HEAD - 1);
                const float b0 = bias[col0], b1 = bias[col0 + 1];
#pragma unroll
                for (int half_m = 0; half_m < 2; half_m++) {
                    const int row = rowBase + wy * 32 + mt * 16 + (lane >> 2) + half_m * 8;
                    const int bb = row >> 11, s = row & (SEQ - 1);
                    float v0 = (acc[mt][nt][half_m * 2]     + b0) * sc;
                    float v1 = (acc[mt][nt][half_m * 2 + 1] + b1) * sc;
                    __half h0 = __float2half_rn(v0), h1 = __float2half_rn(v1);
                    __half l0 = __float2half_rn(v0 - __half2float(h0));
                    __half l1 = __float2half_rn(v1 - __half2float(h1));
                    const size_t e = (((size_t)(bb * N_HEADS + hh)) * SEQ + s) * D_HEAD + d0;
                    *(__half2*)(dH + e) = __halves2half2(h0, h1);
                    *(__half2*)(dL + e) = __halves2half2(l0, l1);
                }
            }
        }
    } else {
#pragma unroll
        for (int mt = 0; mt < 2; mt++)
#pragma unroll
            for (int nt = 0; nt < 8; nt++)
#pragma unroll
                for (int j = 0; j < 4; j++) {
                    const int row = rowBase + wy * 32 + mt * 16 + (lane >> 2) + (j >> 1) * 8;
                    const int col = colBase + wx * 64 + nt * 8 + (lane & 3) * 2 + (j & 1);
                    out[(size_t)row * D_MODEL + col] = acc[mt][nt][j];
                }
    }
}

// ---------------- tensor-core flash attention ----------------
// CTA: 256 thr / 8 warps; BQ=128 (16 rows per warp), BK=64.
// S = qh*kh + ql*kh + qh*kl ; PV = ph*vh + ph*vl + pl*vh
#define FBK    64
#define FST    72                      // smem row stride in halves
#define QTILE  (128 * FST)             // halves
#define KTILE  (64 * FST)              // halves

__device__ __forceinline__ void load_kv(__half* stagep, int kb, int tid,
        const __half* gKh, const __half* gKl, const __half* gVh, const __half* gVl)
{
    const __half* gs[4] = {gKh, gKl, gVh, gVl};
#pragma unroll
    for (int i = 0; i < 8; i++) {
        const int idx = i * 256 + tid;
        const int t = idx >> 9;
        const int rem = idx & 511;
        const int row = rem >> 3;
        const int seg = rem & 7;
        const __half* g = gs[t] + (size_t)(kb + row) * D_HEAD + seg * 8;
        cp_async16(smem_u32(stagep + t * KTILE + row * FST + seg * 8), g);
    }
    asm volatile("cp.async.commit_group;\n" ::: "memory");
}

__global__ __launch_bounds__(256, 1) void flash_mma()
{
    extern __shared__ __half fsm[];
    const int tid = threadIdx.x;
    const int wid = tid >> 5, lane = tid & 31;
    const int qt = blockIdx.x, h = blockIdx.y, b = blockIdx.z;
    const int bh = b * N_HEADS + h;
    const int qBase = qt * 128;
    const size_t gbase = (size_t)bh * SEQ * D_HEAD;

    const __half* gQh = g_Qh + gbase;
    const __half* gQl = g_Ql + gbase;
    const __half* gKh = g_Kh + gbase;
    const __half* gKl = g_Kl + gbase;
    const __half* gVh = g_Vh + gbase;
    const __half* gVl = g_Vl + gbase;

    __half* sQh = fsm;
    __half* sQl = fsm + QTILE;
    __half* stage0 = fsm + 2 * QTILE;
    __half* stage1 = stage0 + 4 * KTILE;

    // Q tile load (group 0)
#pragma unroll
    for (int i = 0; i < 8; i++) {
        const int idx = i * 256 + tid;
        const int t = idx >> 10;
        const int rem = idx & 1023;
        const int row = rem >> 3;
        const int seg = rem & 7;
        const __half* g = (t ? gQl : gQh) + (size_t)(qBase + row) * D_HEAD + seg * 8;
        cp_async16(smem_u32((t ? sQl : sQh) + row * FST + seg * 8), g);
    }
    asm volatile("cp.async.commit_group;\n" ::: "memory");

    const int nkt = 2 * (qt + 1);
    load_kv(stage0, 0, tid, gKh, gKl, gVh, gVl);
    load_kv(stage1, FBK, tid, gKh, gKl, gVh, gVl);

    const int arow = (lane & 7) + ((lane >> 3) & 1) * 8;
    const int acol = (lane >> 4) * 8;
    // non-trans B pattern (K): rows = n (keys), cols = k (d)
    const int brow = (lane & 7) + (lane >> 4) * 8;
    const int bcol = ((lane >> 3) & 1) * 8;
    // trans B pattern (V): rows = k (s), cols = n (d)  — r1 must be k+8 tile
    const int trow = (lane & 7) + ((lane >> 3) & 1) * 8;
    const int tcol = (lane >> 4) * 8;

    uint32_t qh[4][4], ql[4][4];
    float o[8][4];
#pragma unroll
    for (int nb = 0; nb < 8; nb++)
#pragma unroll
        for (int j = 0; j < 4; j++) o[nb][j] = 0.f;
    float m0 = -1e30f, m1 = -1e30f, l0 = 0.f, l1 = 0.f;

    const int row0 = qBase + wid * 16 + (lane >> 2);
    const int row1 = row0 + 8;

    for (int jt = 0; jt < nkt; jt++) {
        __half* stg = (jt & 1) ? stage1 : stage0;
        if (jt < nkt - 1) asm volatile("cp.async.wait_group 1;\n" ::: "memory");
        else              asm volatile("cp.async.wait_group 0;\n" ::: "memory");
        __syncthreads();

        if (jt == 0) {
#pragma unroll
            for (int kk = 0; kk < 4; kk++) {
                const uint32_t off = (uint32_t)(wid * 16 + arow) * (FST * 2)
                                   + (uint32_t)(kk * 16 + acol) * 2;
                ldmat4(qh[kk], smem_u32(sQh) + off);
                ldmat4(ql[kk], smem_u32(sQl) + off);
            }
        }

        const uint32_t sKh = smem_u32(stg);
        const uint32_t sKl = sKh + KTILE * 2;
        const uint32_t sVh = sKh + 2 * KTILE * 2;
        const uint32_t sVl = sKh + 3 * KTILE * 2;

        float s[8][4];
#pragma unroll
        for (int nb = 0; nb < 8; nb++)
#pragma unroll
            for (int j = 0; j < 4; j++) s[nb][j] = 0.f;

        // ---- S = Q K^T (3 split passes) ----
#pragma unroll
        for (int np = 0; np < 4; np++) {
#pragma unroll
            for (int kk = 0; kk < 4; kk++) {
                uint32_t bk4[4];
                const uint32_t off = (uint32_t)(np * 16 + brow) * (FST * 2)
                                   + (uint32_t)(kk * 16 + bcol) * 2;
                ldmat4(bk4, sKh + off);
                mma_fp(s[np * 2],     qh[kk], &bk4[0]);
                mma_fp(s[np * 2 + 1], qh[kk], &bk4[2]);
                mma_fp(s[np * 2],     ql[kk], &bk4[0]);
                mma_fp(s[np * 2 + 1], ql[kk], &bk4[2]);
                ldmat4(bk4, sKl + off);
                mma_fp(s[np * 2],     qh[kk], &bk4[0]);
                mma_fp(s[np * 2 + 1], qh[kk], &bk4[2]);
            }
        }

        // ---- causal mask (partial tiles only) ----
        if (jt >= 2 * qt) {
            const int kb = jt * FBK;
#pragma unroll
            for (int nb = 0; nb < 8; nb++) {
#pragma unroll
                for (int j = 0; j < 4; j++) {
                    const int key = kb + nb * 8 + (lane & 3) * 2 + (j & 1);
                    const int qr = (j < 2) ? row0 : row1;
                    if (key > qr) s[nb][j] = -1e30f;
                }
            }
        }

        // ---- online softmax (exp2 domain) ----
        float mx0 = -1e30f, mx1 = -1e30f;
#pragma unroll
        for (int nb = 0; nb < 8; nb++) {
            mx0 = fmaxf(mx0, fmaxf(s[nb][0], s[nb][1]));
            mx1 = fmaxf(mx1, fmaxf(s[nb][2], s[nb][3]));
        }
        mx0 = fmaxf(mx0, __shfl_xor_sync(0xffffffffu, mx0, 1));
        mx0 = fmaxf(mx0, __shfl_xor_sync(0xffffffffu, mx0, 2));
        mx1 = fmaxf(mx1, __shfl_xor_sync(0xffffffffu, mx1, 1));
        mx1 = fmaxf(mx1, __shfl_xor_sync(0xffffffffu, mx1, 2));
        const float mn0 = fmaxf(m0, mx0), mn1 = fmaxf(m1, mx1);
        const float c0 = fexp2(m0 - mn0), c1 = fexp2(m1 - mn1);
        m0 = mn0; m1 = mn1;

        float sum0 = 0.f, sum1 = 0.f;
#pragma unroll
        for (int nb = 0; nb < 8; nb++) {
            s[nb][0] = fexp2(s[nb][0] - m0); sum0 += s[nb][0];
            s[nb][1] = fexp2(s[nb][1] - m0); sum0 += s[nb][1];
            s[nb][2] = fexp2(s[nb][2] - m1); sum1 += s[nb][2];
            s[nb][3] = fexp2(s[nb][3] - m1); sum1 += s[nb][3];
        }
        sum0 += __shfl_xor_sync(0xffffffffu, sum0, 1);
        sum0 += __shfl_xor_sync(0xffffffffu, sum0, 2);
        sum1 += __shfl_xor_sync(0xffffffffu, sum1, 1);
        sum1 += __shfl_xor_sync(0xffffffffu, sum1, 2);
        l0 = l0 * c0 + sum0;
        l1 = l1 * c1 + sum1;

#pragma unroll
        for (int nb = 0; nb < 8; nb++) {
            o[nb][0] *= c0; o[nb][1] *= c0;
            o[nb][2] *= c1; o[nb][3] *= c1;
        }

        // ---- O += P V (P split, V split; drop pl*vl) ----
#pragma unroll
        for (int kk = 0; kk < 4; kk++) {
            uint32_t aH[4], aL[4];
            aH[0] = pack_h2(s[2 * kk][0], s[2 * kk][1]);
            aH[1] = pack_h2(s[2 * kk][2], s[2 * kk][3]);
            aH[2] = pack_h2(s[2 * kk + 1][0], s[2 * kk + 1][1]);
            aH[3] = pack_h2(s[2 * kk + 1][2], s[2 * kk + 1][3]);
            {
                union { uint32_t u; __half2 h2; } c0u, c1u, c2u, c3u;
                c0u.u = aH[0]; c1u.u = aH[1]; c2u.u = aH[2]; c3u.u = aH[3];
                aL[0] = pack_h2(s[2 * kk][0] - __half2float(__low2half(c0u.h2)),
                                s[2 * kk][1] - __half2float(__high2half(c0u.h2)));
                aL[1] = pack_h2(s[2 * kk][2] - __half2float(__low2half(c1u.h2)),
                                s[2 * kk][3] - __half2float(__high2half(c1u.h2)));
                aL[2] = pack_h2(s[2 * kk + 1][0] - __half2float(__low2half(c2u.h2)),
                                s[2 * kk + 1][1] - __half2float(__high2half(c2u.h2)));
                aL[3] = pack_h2(s[2 * kk + 1][2] - __half2float(__low2half(c3u.h2)),
                                s[2 * kk + 1][3] - __half2float(__high2half(c3u.h2)));
            }
#pragma unroll
            for (int np = 0; np < 4; np++) {
                uint32_t bv[4];
                const uint32_t off = (uint32_t)(kk * 16 + trow) * (FST * 2)
                                   + (uint32_t)(np * 16 + tcol) * 2;
                ldmat4t(bv, sVh + off);
                mma_fp(o[np * 2],     aH, &bv[0]);
                mma_fp(o[np * 2 + 1], aH, &bv[2]);
                mma_fp(o[np * 2],     aL, &bv[0]);
                mma_fp(o[np * 2 + 1], aL, &bv[2]);
                ldmat4t(bv, sVl + off);
                mma_fp(o[np * 2],     aH, &bv[0]);
                mma_fp(o[np * 2 + 1], aH, &bv[2]);
            }
        }

        __syncthreads();
        if (jt + 2 < nkt)
            load_kv(stg, (jt + 2) * FBK, tid, gKh, gKl, gVh, gVl);
    }

    // ---- epilogue: normalize, split-bf16, write g_Ah/g_Al ----
    const float inv0 = 1.f / l0, inv1 = 1.f / l1;
#pragma unroll
    for (int nb = 0; nb < 8; nb++) {
        const int d0 = h * D_HEAD + nb * 8 + (lane & 3) * 2;
#pragma unroll
        for (int half_m = 0; half_m < 2; half_m++) {
            const int row = half_m ? row1 : row0;
            const float inv = half_m ? inv1 : inv0;
            const float v0 = o[nb][half_m * 2] * inv;
            const float v1 = o[nb][half_m * 2 + 1] * inv;
            __nv_bfloat16 h0 = __float2bfloat16_rn(v0), h1 = __float2bfloat16_rn(v1);
            __nv_bfloat16 lo0 = __float2bfloat16_rn(v0 - __bfloat162float(h0));
            __nv_bfloat16 lo1 = __float2bfloat16_rn(v1 - __bfloat162float(h1));
            const size_t e = (size_t)(b * SEQ + row) * D_MODEL + d0;
            uint32_t uh = ((uint32_t)__bfloat16_as_ushort(h1) << 16) | __bfloat16_as_ushort(h0);
            uint32_t ul = ((uint32_t)__bfloat16_as_ushort(lo1) << 16) | __bfloat16_as_ushort(lo0);
            *(uint32_t*)(g_Ah + e) = uh;
            *(uint32_t*)(g_Al + e) = ul;
        }
    }
}

// ---------------- launch ----------------
extern "C" void kernel_launch(void* const* d_in, const int* in_sizes, int n_in,
                              void* d_out, int out_size)
{
    const float* x  = (const float*)d_in[0];
    const float* Wq = (const float*)d_in[1];
    const float* bq = (const float*)d_in[2];
    const float* Wk = (const float*)d_in[3];
    const float* bk = (const float*)d_in[4];
    const float* Wv = (const float*)d_in[5];
    const float* bv = (const float*)d_in[6];
    const float* Wo = (const float*)d_in[7];
    float* out = (float*)d_out;

    const int gemmSmem = 2 * BUFB;   // 81920
    cudaFuncSetAttribute(gemm_mma, cudaFuncAttributeMaxDynamicSharedMemorySize, gemmSmem);
    const int flashSmem = (2 * QTILE + 8 * KTILE) * (int)sizeof(__half);   // 110592
    cudaFuncSetAttribute(flash_mma, cudaFuncAttributeMaxDynamicSharedMemorySize, flashSmem);

    cvt_rm<<<M_ROWS * D_MODEL / 4 / 256, 256>>>(x);
    cvt_wt<<<dim3(D_MODEL / 32, D_MODEL / 32, 4), 256>>>(Wq, Wk, Wv, Wo);
    gemm_mma<<<dim3(D_MODEL / 128, M_ROWS / 128, 3), 256, gemmSmem>>>(bq, bk, bv, nullptr, 0);
    flash_mma<<<dim3(SEQ / 128, N_HEADS, BATCH), 256, flashSmem>>>();
    gemm_mma<<<dim3(D_MODEL / 128, M_ROWS / 128, 1), 256, gemmSmem>>>(nullptr, nullptr, nullptr, out, 1);
}